// round 16
// baseline (speedup 1.0000x reference)
#include <cuda_runtime.h>
#include <math.h>

#define NLAB 17
#define LTOT 19
#define SEQ  256
#define MAXB 8192
#define LN2  0.69314718055994531f
#define FULL 0xffffffffu

__device__ int d_sorted[MAXB];

__constant__ signed char cDP[9] = {0,3,4,7,8,11,12,15,16};
__constant__ signed char cDT[9] = {0,1,4,5,8,9,12,13,16};

// One-block fused sort: histogram + warp-0 register suffix scan + scatter.
__global__ __launch_bounds__(1024)
void crf_sched(const int* __restrict__ lens, int B)
{
    __shared__ int h[SEQ];
    const int t = threadIdx.x;
    if (t < SEQ) h[t] = 0;
    __syncthreads();
    for (int i = t; i < B; i += 1024) atomicAdd(&h[lens[i] - 1], 1);
    __syncthreads();
    if (t < 32) {
        const int base = t * 8;
        int v[8]; int s = 0;
        #pragma unroll
        for (int k = 7; k >= 0; --k) { v[k] = s; s += h[base + k]; }
        int x = s;
        #pragma unroll
        for (int off = 1; off < 32; off <<= 1) {
            int y = __shfl_down_sync(FULL, x, off);
            if (t + off < 32) x += y;
        }
        int e = x - s;
        #pragma unroll
        for (int k = 0; k < 8; ++k) h[base + k] = v[k] + e;
    }
    __syncthreads();
    for (int i = t; i < B; i += 1024) {
        int r = atomicAdd(&h[lens[i] - 1], 1);
        d_sorted[r] = i;
    }
}

#define RESC() { \
    float _mx = fmaxf(fmaxf(p0,p1), fmaxf(p2, fmaxf(p3,p4))); \
    _mx = fmaxf(_mx, __shfl_xor_sync(FULL,_mx,1,4)); \
    _mx = fmaxf(_mx, __shfl_xor_sync(FULL,_mx,2,4)); \
    int _eb = (int)(__float_as_uint(_mx)>>23); \
    float _sc = __uint_as_float((unsigned)(254-_eb)<<23); \
    p0*=_sc; p1*=_sc; p2*=_sc; p3*=_sc; p4*=_sc; C += _eb-127; }

// Two aligned LDG.128 covering the lane's 8-float window at absolute step T.
// O must equal (T & 3) (literal): 17T - O + 4g is a multiple of 4, and lgs is
// 16B aligned, so the casts are legal.
#define FLOAD(R, T, O) { \
    const float4* _a = (const float4*)(lgs + ((T)*17 - (O))); \
    float4 _v0 = __ldg(_a); float4 _v1 = __ldg(_a + 1); \
    R[0]=_v0.x; R[1]=_v0.y; R[2]=_v0.z; R[3]=_v0.w; \
    R[4]=_v1.x; R[5]=_v1.y; R[6]=_v1.z; R[7]=_v1.w; }

// tree-form 9-wide dot products: 3 parallel partials -> depth ~20 cyc
#define DENSE9() \
    float _u0=fmaf(w0[3],_Q3, w0[0]*_Q0); \
    float _v0=fmaf(w0[4],_Q4, w0[1]*_Q1); \
    float _t0=fmaf(w0[5],_Q5, w0[2]*_Q2); \
    float _u1=fmaf(w1[3],_Q3, w1[0]*_Q0); \
    float _v1=fmaf(w1[4],_Q4, w1[1]*_Q1); \
    float _t1=fmaf(w1[5],_Q5, w1[2]*_Q2); \
    float _u2=fmaf(w2[3],_Q3, w2[0]*_Q0); \
    float _v2=fmaf(w2[4],_Q4, w2[1]*_Q1); \
    float _t2=fmaf(w2[5],_Q5, w2[2]*_Q2); \
    _u0=fmaf(w0[6],_Q6,_u0); _v0=fmaf(w0[7],_Q7,_v0); _t0=fmaf(w0[8],_Q8,_t0); \
    _u1=fmaf(w1[6],_Q6,_u1); _v1=fmaf(w1[7],_Q7,_v1); _t1=fmaf(w1[8],_Q8,_t1); \
    _u2=fmaf(w2[6],_Q6,_u2); _v2=fmaf(w2[7],_Q7,_v2); _t2=fmaf(w2[8],_Q8,_t2); \
    float _S0=(_u0+_v0)+_t0; \
    float _S1=(_u1+_v1)+_t1; \
    float _S2=(_u2+_v2)+_t2;

// forward step at absolute T (O = T&3 literal); active for 1 <= T < myM
#define FSTEP(R, T, O) { \
    float _e0=__expf(R[(O)+0]), _e1=__expf(R[(O)+1]), _e2=__expf(R[(O)+2]); \
    float _e3=__expf(R[(O)+3]), _e4=__expf(R[(O)+4]); \
    float _Q0=__shfl_sync(FULL,p0,base+0); \
    float _Q1=__shfl_sync(FULL,p3,base+0); \
    float _Q2=__shfl_sync(FULL,p0,base+1); \
    float _Q3=__shfl_sync(FULL,p3,base+1); \
    float _Q4=__shfl_sync(FULL,p0,base+2); \
    float _Q5=__shfl_sync(FULL,p3,base+2); \
    float _Q6=__shfl_sync(FULL,p0,base+3); \
    float _Q7=__shfl_sync(FULL,p3,base+3); \
    float _Q8=__shfl_sync(FULL,p4,base+3); \
    DENSE9() \
    float _nI = fmaf(wII,p2, wIB*p1); \
    float _nE = fmaf(wEI,p2, wEB*p1); \
    bool _act = ((T) >= 1) && ((T) < myM); \
    p0 = _act ? _e0*_S0 : p0; \
    p1 = _act ? _e1*_S1 : p1; \
    p2 = _act ? _e2*_nI : p2; \
    p3 = _act ? _e3*_nE : p3; \
    p4 = _act ? _e4*_S2 : p4; }

// backward step at absolute T (O = T&3 literal); active for myM <= T <= lenm1
#define BSTEP(R, T, O) { \
    float _u0l=p0*__expf(R[(O)+0]); \
    float _u1l=p1*__expf(R[(O)+1]); \
    float _u2l=p2*__expf(R[(O)+2]); \
    float _u3l=p3*__expf(R[(O)+3]); \
    float _u4l=p4*__expf(R[(O)+4]); \
    float _Q0=__shfl_sync(FULL,_u0l,base+0); \
    float _Q1=__shfl_sync(FULL,_u1l,base+0); \
    float _Q2=__shfl_sync(FULL,_u0l,base+1); \
    float _Q3=__shfl_sync(FULL,_u1l,base+1); \
    float _Q4=__shfl_sync(FULL,_u0l,base+2); \
    float _Q5=__shfl_sync(FULL,_u1l,base+2); \
    float _Q6=__shfl_sync(FULL,_u0l,base+3); \
    float _Q7=__shfl_sync(FULL,_u1l,base+3); \
    float _Q8=__shfl_sync(FULL,_u4l,base+3); \
    DENSE9() \
    float _nB = fmaf(wEB,_u3l, wIB*_u2l); \
    float _nI = fmaf(wEI,_u3l, wII*_u2l); \
    bool _act = ((T) >= myM) && ((T) <= lenm1); \
    p0 = _act ? _S0 : p0; \
    p1 = _act ? _nB : p1; \
    p2 = _act ? _nI : p2; \
    p3 = _act ? _S1 : p3; \
    p4 = _act ? _S2 : p4; }

// Block = 8 warps = 4 (fwd,bwd) MITM pairs, 4 rows/pair (4 lanes/row in
// lanes 0-15; lanes 16-31 mirror rows 0-3: identical addresses/values, writes
// predicated off). 2048 warps total, 2 blocks/SM.
__global__ __launch_bounds__(256, 2)
void crf_main(const float* __restrict__ logits,
              const int*   __restrict__ labels,
              const int*   __restrict__ lens,
              const float* __restrict__ transition,
              float* __restrict__ out, int B)
{
    __shared__ float sT[LTOT*LTOT];
    __shared__ float sA[4][4][20];
    __shared__ float sG[4][4];
    __shared__ int   sC[4][4];

    for (int i = threadIdx.x; i < LTOT*LTOT; i += 256) sT[i] = transition[i];
    __syncthreads();

    const int lane = threadIdx.x & 31;
    const int wId  = threadIdx.x >> 5;
    const int q    = wId >> 1;
    const bool isB = wId & 1;
    const int g    = lane & 3;
    const int r    = (lane >> 2) & 3;      // lanes 16-31 mirror rows 0-3
    const int base = lane & ~3;
    const bool wr  = (lane < 16);

    const int nG  = (B + 3) >> 2;          // groups of 4 rows
    const int per = gridDim.x;
    const int G   = q * per + ((q & 1) ? (per - 1 - (int)blockIdx.x)
                                       : (int)blockIdx.x);
    int rank = G * 4 + r;
    const bool valid = (G < nG) && (rank < B);
    if (!valid) rank = B - 1;
    const int b   = d_sorted[rank];
    const int len = lens[b];
    const int m   = (len + 1) >> 1;
    const int myM = m;

    const float* lg  = logits + (size_t)b * (SEQ*NLAB);
    const int*   lab = labels + (size_t)b * SEQ;
    const int    s0  = 4*g;
    const float* lgs = lg + s0;

    float p0,p1,p2,p3,p4;
    int C = 0;
    float gold = 0.f;

    if (!isB) {
        // ---------------- FORWARD: a_{m-1}, gold over [0,m) ----------------
        for (int t = g; t < m; t += 4) {
            int lt = lab[t];
            int lp = (t == 0) ? (LTOT-2) : lab[t-1];
            gold += lg[t*NLAB + lt] + sT[lt*LTOT + lp];
        }
        gold += __shfl_xor_sync(FULL, gold, 1, 4);
        gold += __shfl_xor_sync(FULL, gold, 2, 4);

        float w0[9], w1[9], w2[9];
        #pragma unroll
        for (int k = 0; k < 9; ++k) {
            int pr = cDP[k];
            w0[k] = expf(sT[s0*LTOT + pr]);
            w1[k] = expf(sT[(s0+1)*LTOT + pr]);
            w2[k] = (g==3) ? expf(sT[16*LTOT + pr]) : 0.f;
        }
        const float wIB = expf(sT[(s0+2)*LTOT + (s0+1)]);
        const float wII = expf(sT[(s0+2)*LTOT + (s0+2)]);
        const float wEB = expf(sT[(s0+3)*LTOT + (s0+1)]);
        const float wEI = expf(sT[(s0+3)*LTOT + (s0+2)]);

        {   // t = 0
            float wst4 = (g==3) ? expf(sT[16*LTOT + 17]) : 0.f;
            p0 = __expf(__ldg(lgs+0)) * expf(sT[s0*LTOT + 17]);
            p1 = __expf(__ldg(lgs+1)) * expf(sT[(s0+1)*LTOT + 17]);
            p2 = __expf(__ldg(lgs+2)) * expf(sT[(s0+2)*LTOT + 17]);
            p3 = __expf(__ldg(lgs+3)) * expf(sT[(s0+3)*LTOT + 17]);
            p4 = __expf(__ldg(lgs+4)) * wst4;
            RESC()
        }

        const int warpM = __reduce_max_sync(FULL, myM);

        float RA[4][8], RB[4][8];
        FLOAD(RA[0],0,0) FLOAD(RA[1],1,1) FLOAD(RA[2],2,2) FLOAD(RA[3],3,3)
        for (int k = 0; k*8 < warpM; ++k) {
            const int t0 = k*8;
            FLOAD(RB[0],t0+4,0) FLOAD(RB[1],t0+5,1)
            FLOAD(RB[2],t0+6,2) FLOAD(RB[3],t0+7,3)
            FSTEP(RA[0],t0+0,0) FSTEP(RA[1],t0+1,1)
            FSTEP(RA[2],t0+2,2) FSTEP(RA[3],t0+3,3)
            FLOAD(RA[0],t0+8,0) FLOAD(RA[1],t0+9,1)
            FLOAD(RA[2],t0+10,2) FLOAD(RA[3],t0+11,3)
            FSTEP(RB[0],t0+4,0) FSTEP(RB[1],t0+5,1)
            FSTEP(RB[2],t0+6,2) FSTEP(RB[3],t0+7,3)
            RESC()
        }

        if (wr) {
            sA[q][r][s0+0]=p0; sA[q][r][s0+1]=p1;
            sA[q][r][s0+2]=p2; sA[q][r][s0+3]=p3;
            if (g==3) sA[q][r][16]=p4;
            if (g==0) { sG[q][r]=gold; sC[q][r]=C; }
        }
        asm volatile("bar.sync %0, %1;" :: "r"(1+q), "r"(64) : "memory");
    } else {
        // ---------------- BACKWARD: b_m, gold over [m,len) + end ----------
        for (int t = m + g; t < len; t += 4) {
            int lt = lab[t];
            gold += lg[t*NLAB + lt] + sT[lt*LTOT + lab[t-1]];
        }
        if (g==0) gold += sT[(LTOT-1)*LTOT + lab[len-1]];
        gold += __shfl_xor_sync(FULL, gold, 1, 4);
        gold += __shfl_xor_sync(FULL, gold, 2, 4);

        float w0[9], w1[9], w2[9];
        #pragma unroll
        for (int k = 0; k < 9; ++k) {
            int dt = cDT[k];
            w0[k] = expf(sT[dt*LTOT + s0]);
            w1[k] = expf(sT[dt*LTOT + (s0+3)]);
            w2[k] = (g==3) ? expf(sT[dt*LTOT + 16]) : 0.f;
        }
        const float wIB = expf(sT[(s0+2)*LTOT + (s0+1)]);
        const float wII = expf(sT[(s0+2)*LTOT + (s0+2)]);
        const float wEB = expf(sT[(s0+3)*LTOT + (s0+1)]);
        const float wEI = expf(sT[(s0+3)*LTOT + (s0+2)]);

        p0 = expf(sT[18*LTOT + s0]);
        p1 = expf(sT[18*LTOT + (s0+1)]);
        p2 = expf(sT[18*LTOT + (s0+2)]);
        p3 = expf(sT[18*LTOT + (s0+3)]);
        p4 = (g==3) ? expf(sT[18*LTOT + 16]) : 0.f;

        const int lenm1  = len - 1;
        const int warpT1 = __reduce_max_sync(FULL, lenm1);
        const int tLow   = __reduce_min_sync(FULL, myM);
        const int kHi = warpT1 >> 3;
        const int kLo = tLow >> 3;

        float RA[4][8], RB[4][8];
        {
            const int t0 = kHi*8;
            FLOAD(RA[0],t0+7,3) FLOAD(RA[1],t0+6,2)
            FLOAD(RA[2],t0+5,1) FLOAD(RA[3],t0+4,0)
        }
        for (int k = kHi; k >= kLo; --k) {
            const int t0 = k*8;
            FLOAD(RB[0],t0+3,3) FLOAD(RB[1],t0+2,2)
            FLOAD(RB[2],t0+1,1) FLOAD(RB[3],t0+0,0)
            BSTEP(RA[0],t0+7,3) BSTEP(RA[1],t0+6,2)
            BSTEP(RA[2],t0+5,1) BSTEP(RA[3],t0+4,0)
            if (k > kLo) {
                const int t1 = t0 - 8;
                FLOAD(RA[0],t1+7,3) FLOAD(RA[1],t1+6,2)
                FLOAD(RA[2],t1+5,1) FLOAD(RA[3],t1+4,0)
            }
            BSTEP(RB[0],t0+3,3) BSTEP(RB[1],t0+2,2)
            BSTEP(RB[2],t0+1,1) BSTEP(RB[3],t0+0,0)
            RESC()
        }

        asm volatile("bar.sync %0, %1;" :: "r"(1+q), "r"(64) : "memory");

        float ss = p0 * sA[q][r][s0+0];
        ss = fmaf(p1, sA[q][r][s0+1], ss);
        ss = fmaf(p2, sA[q][r][s0+2], ss);
        ss = fmaf(p3, sA[q][r][s0+3], ss);
        ss = fmaf(p4, sA[q][r][s0+4], ss);
        ss += __shfl_xor_sync(FULL, ss, 1, 4);
        ss += __shfl_xor_sync(FULL, ss, 2, 4);

        if (g==0 && wr && valid) {
            float gT = gold + sG[q][r];
            int   cT = C + sC[q][r];
            out[b] = gT - ((float)cT*LN2 + logf(ss));
        }
    }
}

extern "C" void kernel_launch(void* const* d_in, const int* in_sizes, int n_in,
                              void* d_out, int out_size)
{
    const float* logits     = (const float*)d_in[0];
    const int*   labels     = (const int*)  d_in[1];
    const int*   lens       = (const int*)  d_in[2];
    const float* transition = (const float*)d_in[3];
    float*       out        = (float*)d_out;

    int B = in_sizes[2];

    crf_sched<<<1, 1024>>>(lens, B);

    int nGroups = (B + 3) / 4;           // 4 rows per pair now
    int grid = (nGroups + 3) / 4;        // 4 pairs per block
    if (grid < 296) grid = 296;          // 2 blocks per SM
    crf_main<<<grid, 256>>>(logits, labels, lens, transition, out, B);
}